// round 1
// baseline (speedup 1.0000x reference)
#include <cuda_runtime.h>
#include <cuda_bf16.h>

// Problem constants (fixed by the reference setup)
#define B_  2
#define L_  24
#define C_  16
#define H_  64
#define W_  64
#define HW_ 4096

// out[b,t,c,h,w] = sum_{k<=t} bilinear_sample( images[b,k,c],
//                     grid = pixel_center(h,w) + 32*(cumflow[t]-cumflow[k]) )
// with x wrapped into [-0.5, 63.5) and zeros padding at borders.
//
// One thread per (b,t,h,w); 16 channel accumulators in registers; the
// relative flow telescopes so we accumulate it on the fly (no cumsum pass).
__global__ __launch_bounds__(256) void gsp_kernel(
    const float* __restrict__ flows,    // [B, L, 2, H, W]
    const float* __restrict__ images,   // [B, L, C, H, W]
    float* __restrict__ out)            // [B, L, C, H, W]
{
    const int b   = blockIdx.z;
    const int t   = blockIdx.y;
    const int pix = blockIdx.x * blockDim.x + threadIdx.x;   // 0..4095
    const int h   = pix >> 6;
    const int w   = pix & 63;

    float acc[C_];
#pragma unroll
    for (int c = 0; c < C_; ++c) acc[c] = 0.f;

    float relx = 0.f, rely = 0.f;
    const float* flowbase = flows + (size_t)b * L_ * 2 * HW_ + pix;

    for (int k = t; k >= 0; --k) {
        if (k < t) {
            // rel(k) = rel(k+1) + flow[k+1]
            const float* fp = flowbase + (size_t)(k + 1) * 2 * HW_;
            relx += fp[0];
            rely += fp[HW_];
        }

        // sample coordinate (align_corners=False): base grid == pixel centers
        float ix = (float)w + 32.f * relx;
        ix -= 64.f * floorf((ix + 0.5f) * 0.015625f);     // wrap x into [-0.5, 63.5)
        float iy = (float)h + 32.f * rely;

        float x0f = floorf(ix), y0f = floorf(iy);
        int   x0  = (int)x0f,   y0  = (int)y0f;
        float wx1 = ix - x0f,   wy1 = iy - y0f;
        float wx0 = 1.f - wx1,  wy0 = 1.f - wy1;

        // x0 in [-1, 63] by construction; x1 = x0+1 in [0, 64]
        bool vx0 = (x0 >= 0);
        bool vx1 = (x0 < W_ - 1);
        bool vy0 = (y0 >= 0) && (y0 <= H_ - 1);
        bool vy1 = (y0 >= -1) && (y0 < H_ - 1);

        float w00 = wx0 * wy0 * (float)(vx0 && vy0);
        float w01 = wx1 * wy0 * (float)(vx1 && vy0);
        float w10 = wx0 * wy1 * (float)(vx0 && vy1);
        float w11 = wx1 * wy1 * (float)(vx1 && vy1);

        int cx0 = max(x0, 0),             cx1 = min(x0 + 1, W_ - 1);
        int cy0 = min(max(y0, 0), H_ - 1), cy1 = min(max(y0 + 1, 0), H_ - 1);

        const int o00 = cy0 * W_ + cx0, o01 = cy0 * W_ + cx1;
        const int o10 = cy1 * W_ + cx0, o11 = cy1 * W_ + cx1;

        const float* ib = images + ((size_t)b * L_ + k) * C_ * HW_;
#pragma unroll
        for (int c = 0; c < C_; ++c) {
            const float* p = ib + c * HW_;
            acc[c] += w00 * p[o00] + w01 * p[o01] + w10 * p[o10] + w11 * p[o11];
        }
    }

    float* op = out + ((size_t)b * L_ + t) * C_ * HW_ + pix;
#pragma unroll
    for (int c = 0; c < C_; ++c) op[c * HW_] = acc[c];
}

extern "C" void kernel_launch(void* const* d_in, const int* in_sizes, int n_in,
                              void* d_out, int out_size)
{
    const float* flows  = (const float*)d_in[0];   // [2,24,2,64,64]
    const float* images = (const float*)d_in[1];   // [2,24,16,64,64]
    float*       out    = (float*)d_out;           // [2,24,16,64,64]

    dim3 grid(HW_ / 256, L_, B_);                  // (16, 24, 2)
    gsp_kernel<<<grid, 256>>>(flows, images, out);
}